// round 6
// baseline (speedup 1.0000x reference)
#include <cuda_runtime.h>

// ---------------- problem constants ----------------
#define Bn    64
#define Tn    4096
#define KPn   67      // keypoints: 25 body + 21 + 21
#define KIN   134     // 2*K input features
#define Dn    256     // hidden
#define Cn    7       // classes
#define TT    64      // timesteps per sub-tile
#define NSUB  4       // sub-tiles per block
#define TBLK  (TT*NSUB)   // 256 timesteps per block
#define PLD2  66      // pos tile row stride in u64 units (64 + 2 pad)

// scratch: pooled [B, D]. Zero-initialized statically; bn_cls_kernel
// re-zeroes it after consuming, so every graph replay sees zeros.
__device__ float g_pooled[Bn * Dn];

// length may arrive as int32 or int64 depending on jax x64 config.
// int64 little-endian view as int32: [val,0,val,0,...]; length>=1 and
// <=4096 so L[1]==0 uniquely identifies the int64 layout (in-bounds
// either way: int32 reads L[0..63], int64-view reads L[0..127]).
static __device__ __forceinline__ int get_len(const int* __restrict__ L, int b) {
    return (L[1] == 0) ? L[2 * b] : L[b];
}

static __device__ __forceinline__ unsigned long long dup2(float x) {
    unsigned long long r;
    asm("mov.b64 %0, {%1, %1};" : "=l"(r) : "f"(x));
    return r;
}
static __device__ __forceinline__ void fma2(unsigned long long& d,
                                            unsigned long long a,
                                            unsigned long long b) {
    // packed fp32x2 FMA -> SASS FFMA2 (sm_100+), full fp32 per-lane precision
    asm("fma.rn.f32x2 %0, %1, %2, %0;" : "+l"(d) : "l"(a), "l"(b));
}
static __device__ __forceinline__ float2 unpack2(unsigned long long v) {
    float2 f;
    asm("mov.b64 {%0, %1}, %2;" : "=f"(f.x), "=f"(f.y) : "l"(v));
    return f;
}

// ---------------------------------------------------------------------------
// Kernel 1: fused gather/gate + GEMM(pos @ W1) + masked max-pool
// grid = (Tn/TBLK, Bn), block = 256.
// Per-thread 8t x 8d tile; accumulators are f32x2 pairs along d.
// pos values stored PRE-DUPLICATED as u64 {v,v} so the FFMA2 inner loop is
// pure LDS.128 + FFMA2 (no pack MOVs). W1 pairs come straight from its
// natural [k][d] layout. Blocks fully past length[b] exit immediately.
// ---------------------------------------------------------------------------
__global__ __launch_bounds__(256, 1)
void gemm_pool_kernel(const float* __restrict__ body,
                      const float* __restrict__ hr,
                      const float* __restrict__ hl,
                      const int*   __restrict__ L,
                      const float* __restrict__ W1,
                      const float* __restrict__ b1)
{
    extern __shared__ float smem[];
    float* W1s = smem;                                   // 134*256 f = 137216 B
    unsigned long long* poss2 =
        reinterpret_cast<unsigned long long*>(smem + KIN * Dn); // 134*66 u64 = 70752 B
    float* b1s = reinterpret_cast<float*>(poss2 + KIN * PLD2);  // 256 f

    const int tid = threadIdx.x;
    const int b   = blockIdx.y;
    const int len = get_len(L, b);
    const int t0  = blockIdx.x * TBLK;
    if (t0 >= len) return;                 // uniform per block: safe w/ syncs

    // stage W1 (natural [k][d] layout: consecutive d pairs = FFMA2 operand) + b1
    {
        const float4* g = reinterpret_cast<const float4*>(W1);
        float4* s = reinterpret_cast<float4*>(W1s);
        #pragma unroll 4
        for (int i = tid; i < KIN * Dn / 4; i += 256) s[i] = g[i];
        b1s[tid] = b1[tid];
    }

    const int tt = tid & 7;    // t-group: owns t_local in [tt*8, tt*8+8)
    const int dg = tid >> 3;   // d-group: owns d in [dg*8, dg*8+8)
    const int d0 = dg << 3;

    float vmax[8];
    #pragma unroll
    for (int j = 0; j < 8; j++) vmax[j] = -3.402823466e38f;

    for (int s = 0; s < NSUB; s++) {
        const int t0s = t0 + s * TT;
        if (t0s >= len) break;             // uniform per block
        __syncthreads();                   // protect poss2 reuse (also W1 @ s=0)

        // gather + confidence-gate, store duplicated {v,v} u64, layout [k][t].
        // Mapping: 64 consecutive threads share kp, cover consecutive tl ->
        // conflict-free STS.64 (consecutive banks within each 64-lane group).
        for (int p = tid; p < KPn * TT; p += 256) {
            const int kp = p >> 6;         // 0..66
            const int tl = p & 63;
            const size_t t = (size_t)(t0s + tl);
            const float* src;
            if (kp < 25)      src = body + ((size_t)b * Tn + t) * 75 + kp * 3;
            else if (kp < 46) src = hr   + ((size_t)b * Tn + t) * 63 + (kp - 25) * 3;
            else              src = hl   + ((size_t)b * Tn + t) * 63 + (kp - 46) * 3;
            const float x = src[0], y = src[1], c = src[2];
            const float gate = (c > 0.1f) ? 1.0f : 0.0f;
            poss2[(2 * kp    ) * PLD2 + tl] = dup2(x * gate);
            poss2[(2 * kp + 1) * PLD2 + tl] = dup2(y * gate);
        }
        __syncthreads();

        unsigned long long acc[8][4];
        #pragma unroll
        for (int i = 0; i < 8; i++)
            #pragma unroll
            for (int j = 0; j < 4; j++) acc[i][j] = 0ULL;

        #pragma unroll 2
        for (int k = 0; k < KIN; k++) {
            // 8 duplicated t-values: 64B contiguous -> 4x LDS.128
            const ulonglong2* pr =
                reinterpret_cast<const ulonglong2*>(poss2 + k * PLD2 + tt * 8);
            const ulonglong2 q0 = pr[0], q1 = pr[1], q2 = pr[2], q3 = pr[3];
            unsigned long long P[8] = {q0.x, q0.y, q1.x, q1.y,
                                       q2.x, q2.y, q3.x, q3.y};
            // 8 W values (4 pairs): 32B contiguous -> 2x LDS.128 (8-lane bcast)
            const ulonglong2* wr =
                reinterpret_cast<const ulonglong2*>(W1s + k * Dn + d0);
            const ulonglong2 wa = wr[0], wb = wr[1];
            unsigned long long W[4] = {wa.x, wa.y, wb.x, wb.y};
            #pragma unroll
            for (int i = 0; i < 8; i++)
                #pragma unroll
                for (int j = 0; j < 4; j++)
                    fma2(acc[i][j], P[i], W[j]);
        }

        // running max over this sub-tile (bias/relu deferred)
        if (t0s + TT <= len) {             // full tile: no mask predicate
            #pragma unroll
            for (int i = 0; i < 8; i++)
                #pragma unroll
                for (int j = 0; j < 4; j++) {
                    const float2 v = unpack2(acc[i][j]);
                    vmax[2 * j    ] = fmaxf(vmax[2 * j    ], v.x);
                    vmax[2 * j + 1] = fmaxf(vmax[2 * j + 1], v.y);
                }
        } else {
            const int nval = len - t0s;
            #pragma unroll
            for (int i = 0; i < 8; i++) {
                if (tt * 8 + i < nval) {
                    #pragma unroll
                    for (int j = 0; j < 4; j++) {
                        const float2 v = unpack2(acc[i][j]);
                        vmax[2 * j    ] = fmaxf(vmax[2 * j    ], v.x);
                        vmax[2 * j + 1] = fmaxf(vmax[2 * j + 1], v.y);
                    }
                }
            }
        }
    }

    // reduce over the 8 t-groups (lanes tt=0..7 within each dg share d-range)
    #pragma unroll
    for (int j = 0; j < 8; j++) {
        vmax[j] = fmaxf(vmax[j], __shfl_xor_sync(0xffffffffu, vmax[j], 1));
        vmax[j] = fmaxf(vmax[j], __shfl_xor_sync(0xffffffffu, vmax[j], 2));
        vmax[j] = fmaxf(vmax[j], __shfl_xor_sync(0xffffffffu, vmax[j], 4));
    }
    if (tt == 0) {
        #pragma unroll
        for (int j = 0; j < 8; j++) {
            // max_t relu(h+b1) = max(0, max_t h + b1); values >= 0 so
            // int-bit atomicMax is exact. -inf + b1 -> clamped to 0, harmless.
            const float val = fmaxf(vmax[j] + b1s[d0 + j], 0.0f);
            atomicMax(reinterpret_cast<int*>(&g_pooled[b * Dn + d0 + j]),
                      __float_as_int(val));
        }
    }
}

// ---------------------------------------------------------------------------
// Kernel 2: BatchNorm (batch stats, two-pass) + classifier. One block of 256
// (tid d-mapping requires blockDim.x == Dn == 256). Re-zeroes g_pooled at
// the end so the next graph replay starts from zeros.
// ---------------------------------------------------------------------------
__global__ __launch_bounds__(256, 1)
void bn_cls_kernel(const float* __restrict__ gamma,
                   const float* __restrict__ beta,
                   const float* __restrict__ Wc,
                   const float* __restrict__ bc,
                   float* __restrict__ out)
{
    __shared__ float scale_s[Dn], shift_s[Dn];
    const int tid = threadIdx.x;
    {
        const int d = tid;
        float s = 0.0f;
        #pragma unroll 4
        for (int b = 0; b < Bn; b++) s += g_pooled[b * Dn + d];
        const float mean = s * (1.0f / Bn);
        float v = 0.0f;
        #pragma unroll 4
        for (int b = 0; b < Bn; b++) {
            const float df = g_pooled[b * Dn + d] - mean;
            v += df * df;
        }
        const float var = v * (1.0f / Bn);          // ddof=0, matches jnp.var
        const float sc  = gamma[d] / sqrtf(var + 1e-5f);
        scale_s[d] = sc;
        shift_s[d] = beta[d] - mean * sc;
    }
    __syncthreads();
    for (int idx = tid; idx < Bn * Cn; idx += 256) {
        const int bb = idx / Cn;
        const int c  = idx - bb * Cn;
        float acc = bc[c];
        #pragma unroll 4
        for (int d = 0; d < Dn; d++)
            acc += (g_pooled[bb * Dn + d] * scale_s[d] + shift_s[d])
                   * Wc[d * Cn + c];
        out[idx] = acc;   // idx == bb*7 + c
    }
    __syncthreads();                       // all reads of g_pooled done
    #pragma unroll 4
    for (int i = tid; i < Bn * Dn; i += 256) g_pooled[i] = 0.0f;
}

// ---------------------------------------------------------------------------
extern "C" void kernel_launch(void* const* d_in, const int* in_sizes, int n_in,
                              void* d_out, int out_size)
{
    (void)in_sizes; (void)n_in; (void)out_size;
    const float* body  = (const float*)d_in[0];
    const float* hrp   = (const float*)d_in[1];
    const float* hlp   = (const float*)d_in[2];
    const int*   len   = (const int*)d_in[3];
    const float* W1    = (const float*)d_in[4];
    const float* b1    = (const float*)d_in[5];
    const float* gamma = (const float*)d_in[6];
    const float* beta  = (const float*)d_in[7];
    const float* Wc    = (const float*)d_in[8];
    const float* bc    = (const float*)d_in[9];
    float* out = (float*)d_out;

    // smem: W1 137216 + poss2 70752 + b1 1024 = 208992 B (< 227KB dyn limit)
    const int smem1 = KIN * Dn * 4 + KIN * PLD2 * 8 + Dn * 4;
    cudaFuncSetAttribute(gemm_pool_kernel,
                         cudaFuncAttributeMaxDynamicSharedMemorySize, smem1);

    dim3 grid(Tn / TBLK, Bn);
    gemm_pool_kernel<<<grid, 256, smem1>>>(body, hrp, hlp, len, W1, b1);
    bn_cls_kernel<<<1, 256>>>(gamma, beta, Wc, bc, out);
}

// round 15
// speedup vs baseline: 1.8012x; 1.8012x over previous
#include <cuda_runtime.h>

// ---------------- problem constants ----------------
#define Bn    64
#define Tn    4096
#define KPn   67      // keypoints: 25 body + 21 + 21
#define KIN   134     // 2*K input features
#define Dn    256     // hidden
#define DH    128     // d-columns per CTA (D split across gridDim.z=2)
#define Cn    7       // classes
#define TT    64      // timesteps per sub-tile
#define NSUB  4       // sub-tiles per block
#define TBLK  (TT*NSUB)   // 256 timesteps per block
#define POSLD 68      // pos tile row stride (floats)

// scratch (allocation-free rule -> __device__ globals)
__device__ float g_pooled[Bn * Dn];   // static zero-init; re-zeroed by cls
__device__ float g_scale[Dn];
__device__ float g_shift[Dn];

// length may arrive as int32 or int64 depending on jax x64 config.
// int64 LE view as int32: [val,0,val,0,...]; 1<=len<=4096 so L[1]==0
// uniquely identifies int64 layout (reads in-bounds either way).
static __device__ __forceinline__ int get_len(const int* __restrict__ L, int b) {
    return (L[1] == 0) ? L[2 * b] : L[b];
}

static __device__ __forceinline__ unsigned long long dup2(float x) {
    unsigned long long r;
    asm("mov.b64 %0, {%1, %1};" : "=l"(r) : "f"(x));
    return r;
}
static __device__ __forceinline__ void fma2(unsigned long long& d,
                                            unsigned long long a,
                                            unsigned long long b) {
    // packed fp32x2 FMA -> SASS FFMA2, full fp32 per-lane precision
    asm("fma.rn.f32x2 %0, %1, %2, %0;" : "+l"(d) : "l"(a), "l"(b));
}
static __device__ __forceinline__ float2 unpack2(unsigned long long v) {
    float2 f;
    asm("mov.b64 {%0, %1}, %2;" : "=f"(f.x), "=f"(f.y) : "l"(v));
    return f;
}

// ---------------------------------------------------------------------------
// Kernel 1: fused gather/gate + GEMM(pos @ W1-half) + masked max-pool
// grid = (Tn/TBLK, Bn, 2), block = 256, 2 CTAs/SM (smem ~103KB each).
// CTA z owns d in [z*128, z*128+128). Per-thread 8t x 4d, f32x2 acc pairs.
// ---------------------------------------------------------------------------
__global__ __launch_bounds__(256, 2)
void gemm_pool_kernel(const float* __restrict__ body,
                      const float* __restrict__ hr,
                      const float* __restrict__ hl,
                      const int*   __restrict__ L,
                      const float* __restrict__ W1,
                      const float* __restrict__ b1)
{
    extern __shared__ float smem[];
    float* W1s  = smem;                    // KIN*DH   = 17152 floats (68608 B)
    float* poss = smem + KIN * DH;         // KIN*POSLD = 9112 floats (36448 B)
    float* b1s  = poss + KIN * POSLD;      // DH floats

    const int tid = threadIdx.x;
    const int b   = blockIdx.y;
    const int len = get_len(L, b);
    const int t0  = blockIdx.x * TBLK;
    if (t0 >= len) return;                 // uniform per block
    const int d0cta = blockIdx.z * DH;

    // stage this CTA's half of W1 ([k][0..127]) + b1 slice
    {
        const float4* g = reinterpret_cast<const float4*>(W1);
        float4* s = reinterpret_cast<float4*>(W1s);
        #pragma unroll 4
        for (int i = tid; i < KIN * DH / 4; i += 256) {
            const int k = i >> 5;               // DH/4 = 32 float4 per row
            const int c4 = i & 31;
            s[i] = g[k * (Dn / 4) + (d0cta >> 2) + c4];
        }
        if (tid < DH) b1s[tid] = b1[d0cta + tid];
    }

    const int tt   = tid & 7;          // t-group: t_local in [tt*8, tt*8+8)
    const int dg   = tid >> 3;         // d-group 0..31: d = d0cta + dg*4 ..+4
    const int dloc = dg << 2;

    float vmax[4];
    #pragma unroll
    for (int j = 0; j < 4; j++) vmax[j] = -3.402823466e38f;

    for (int s = 0; s < NSUB; s++) {
        const int t0s = t0 + s * TT;
        if (t0s >= len) break;             // uniform per block
        __syncthreads();                   // protect poss reuse (also W1 @ s=0)

        // gather + confidence-gate into pos tile [k][t] (float).
        // 64 consecutive threads share kp, cover consecutive tl ->
        // conflict-free STS.32, no integer div.
        for (int p = tid; p < KPn * TT; p += 256) {
            const int kp = p >> 6;
            const int tl = p & 63;
            const size_t t = (size_t)(t0s + tl);
            const float* src;
            if (kp < 25)      src = body + ((size_t)b * Tn + t) * 75 + kp * 3;
            else if (kp < 46) src = hr   + ((size_t)b * Tn + t) * 63 + (kp - 25) * 3;
            else              src = hl   + ((size_t)b * Tn + t) * 63 + (kp - 46) * 3;
            const float x = src[0], y = src[1], c = src[2];
            const float gate = (c > 0.1f) ? 1.0f : 0.0f;
            poss[(2 * kp    ) * POSLD + tl] = x * gate;
            poss[(2 * kp + 1) * POSLD + tl] = y * gate;
        }
        __syncthreads();

        unsigned long long acc[8][2];
        #pragma unroll
        for (int i = 0; i < 8; i++) { acc[i][0] = 0ULL; acc[i][1] = 0ULL; }

        #pragma unroll 2
        for (int k = 0; k < KIN; k++) {
            // 8 t-values: 32B -> 2x LDS.128 (2 phases each; 256B-unique min)
            const float4* pr =
                reinterpret_cast<const float4*>(poss + k * POSLD + tt * 8);
            const float4 p0 = pr[0];
            const float4 p1 = pr[1];
            unsigned long long P[8];
            P[0] = dup2(p0.x); P[1] = dup2(p0.y);
            P[2] = dup2(p0.z); P[3] = dup2(p0.w);
            P[4] = dup2(p1.x); P[5] = dup2(p1.y);
            P[6] = dup2(p1.z); P[7] = dup2(p1.w);
            // 4 W floats (2 d-pairs): 1x LDS.128, 8-way bcast (1 phase)
            const ulonglong2 w =
                *reinterpret_cast<const ulonglong2*>(W1s + k * DH + dloc);
            #pragma unroll
            for (int i = 0; i < 8; i++) {
                fma2(acc[i][0], P[i], w.x);
                fma2(acc[i][1], P[i], w.y);
            }
        }

        // running max over this sub-tile (bias/relu deferred)
        if (t0s + TT <= len) {             // full tile: no mask predicate
            #pragma unroll
            for (int i = 0; i < 8; i++)
                #pragma unroll
                for (int j = 0; j < 2; j++) {
                    const float2 v = unpack2(acc[i][j]);
                    vmax[2 * j    ] = fmaxf(vmax[2 * j    ], v.x);
                    vmax[2 * j + 1] = fmaxf(vmax[2 * j + 1], v.y);
                }
        } else {
            const int nval = len - t0s;
            #pragma unroll
            for (int i = 0; i < 8; i++) {
                if (tt * 8 + i < nval) {
                    #pragma unroll
                    for (int j = 0; j < 2; j++) {
                        const float2 v = unpack2(acc[i][j]);
                        vmax[2 * j    ] = fmaxf(vmax[2 * j    ], v.x);
                        vmax[2 * j + 1] = fmaxf(vmax[2 * j + 1], v.y);
                    }
                }
            }
        }
    }

    // reduce over the 8 t-groups (lanes within a dg differ only in tt)
    #pragma unroll
    for (int j = 0; j < 4; j++) {
        vmax[j] = fmaxf(vmax[j], __shfl_xor_sync(0xffffffffu, vmax[j], 1));
        vmax[j] = fmaxf(vmax[j], __shfl_xor_sync(0xffffffffu, vmax[j], 2));
        vmax[j] = fmaxf(vmax[j], __shfl_xor_sync(0xffffffffu, vmax[j], 4));
    }
    if (tt == 0) {
        #pragma unroll
        for (int j = 0; j < 4; j++) {
            // max_t relu(h+b1) = max(0, max_t h + b1); values >= 0 so
            // int-bit atomicMax vs zero-init is exact.
            const float val = fmaxf(vmax[j] + b1s[dloc + j], 0.0f);
            atomicMax(reinterpret_cast<int*>(
                          &g_pooled[b * Dn + d0cta + dloc + j]),
                      __float_as_int(val));
        }
    }
}

// ---------------------------------------------------------------------------
// Kernel 2a: BN stats per d (two-pass; second pass L1-resident). 1x256.
// ---------------------------------------------------------------------------
__global__ __launch_bounds__(256, 1)
void bn_stats_kernel(const float* __restrict__ gamma,
                     const float* __restrict__ beta)
{
    const int d = threadIdx.x;
    float s = 0.0f;
    #pragma unroll 8
    for (int b = 0; b < Bn; b++) s += g_pooled[b * Dn + d];
    const float mean = s * (1.0f / Bn);
    float v = 0.0f;
    #pragma unroll 8
    for (int b = 0; b < Bn; b++) {
        const float df = g_pooled[b * Dn + d] - mean;
        v += df * df;
    }
    const float var = v * (1.0f / Bn);              // ddof=0, matches jnp.var
    const float sc  = gamma[d] / sqrtf(var + 1e-5f);
    g_scale[d] = sc;
    g_shift[d] = beta[d] - mean * sc;
}

// ---------------------------------------------------------------------------
// Kernel 2b: classifier. grid=Bn, block=224 (7 warps; warp w -> class w).
// Each block BN-transforms its pooled row into smem, then warp dots.
// Block b re-zeroes its g_pooled row afterward (graph-replay hygiene).
// ---------------------------------------------------------------------------
__global__ __launch_bounds__(224, 1)
void cls_kernel(const float* __restrict__ Wc,
                const float* __restrict__ bc,
                float* __restrict__ out)
{
    __shared__ float bns[Dn];
    const int b    = blockIdx.x;
    const int tid  = threadIdx.x;
    const int c    = tid >> 5;       // warp id = class
    const int lane = tid & 31;

    for (int d = tid; d < Dn; d += 224)
        bns[d] = g_pooled[b * Dn + d] * g_scale[d] + g_shift[d];
    __syncthreads();

    float acc = 0.0f;
    #pragma unroll
    for (int i = 0; i < 8; i++) {
        const int d = lane + i * 32;
        acc += bns[d] * Wc[d * Cn + c];
    }
    #pragma unroll
    for (int o = 16; o > 0; o >>= 1)
        acc += __shfl_xor_sync(0xffffffffu, acc, o);
    if (lane == 0) out[b * Cn + c] = acc + bc[c];

    __syncthreads();                 // all reads of this row done
    for (int d = tid; d < Dn; d += 224) g_pooled[b * Dn + d] = 0.0f;
}

// ---------------------------------------------------------------------------
extern "C" void kernel_launch(void* const* d_in, const int* in_sizes, int n_in,
                              void* d_out, int out_size)
{
    (void)in_sizes; (void)n_in; (void)out_size;
    const float* body  = (const float*)d_in[0];
    const float* hrp   = (const float*)d_in[1];
    const float* hlp   = (const float*)d_in[2];
    const int*   len   = (const int*)d_in[3];
    const float* W1    = (const float*)d_in[4];
    const float* b1    = (const float*)d_in[5];
    const float* gamma = (const float*)d_in[6];
    const float* beta  = (const float*)d_in[7];
    const float* Wc    = (const float*)d_in[8];
    const float* bc    = (const float*)d_in[9];
    float* out = (float*)d_out;

    // smem/CTA: 68608 + 36448 + 512 = 105568 B -> 2 CTAs/SM
    const int smem1 = (KIN * DH + KIN * POSLD + DH) * (int)sizeof(float);
    cudaFuncSetAttribute(gemm_pool_kernel,
                         cudaFuncAttributeMaxDynamicSharedMemorySize, smem1);

    dim3 grid(Tn / TBLK, Bn, 2);
    gemm_pool_kernel<<<grid, 256, smem1>>>(body, hrp, hlp, len, W1, b1);
    bn_stats_kernel<<<1, 256>>>(gamma, beta);
    cls_kernel<<<Bn, 224>>>(Wc, bc, out);
}